// round 17
// baseline (speedup 1.0000x reference)
#include <cuda_runtime.h>
#include <cuda_bf16.h>
#include <cuda_fp16.h>
#include <cstdint>

#define B_   2
#define N_   4096
#define INF_ 256
#define H_   4
#define F_   64
#define BN_  (B_ * N_)      // 8192
#define HF_  (H_ * F_)      // 256
#define MAXD   512
#define MAXD_S 128
#define PSTR   (MAXD_S + 4)

#define FUSED_BLOCKS 256    // (BN_/GBM=128) * (HF_/GBN=64) = 64*4
#define CSR_ROWS_PER_BLOCK (N_ / FUSED_BLOCKS)   // 16

// ---------------- scratch (device globals) ----------------------------------
__device__ __align__(16) __half g_h16[BN_ * HF_];
__device__ __align__(16) float  g_ssrc[BN_ * H_];
__device__ __align__(16) float  g_sdst[BN_ * H_];
__device__ int g_nbrs[N_ * MAXD];
__device__ int g_deg[N_];

// ---------------------------------------------------------------------------
__device__ __forceinline__ uint32_t tf32_rna(float a) {
    uint32_t u;
    asm("cvt.rna.tf32.f32 %0, %1;" : "=r"(u) : "f"(a));
    return u;
}

__device__ __forceinline__ void mma_tf32(float c[4],
                                         uint32_t a0, uint32_t a1, uint32_t a2, uint32_t a3,
                                         uint32_t b0, uint32_t b1)
{
    asm volatile(
        "mma.sync.aligned.m16n8k8.row.col.f32.tf32.tf32.f32 "
        "{%0,%1,%2,%3},{%4,%5,%6,%7},{%8,%9},{%0,%1,%2,%3};"
        : "+f"(c[0]), "+f"(c[1]), "+f"(c[2]), "+f"(c[3])
        : "r"(a0), "r"(a1), "r"(a2), "r"(a3), "r"(b0), "r"(b1));
}

__device__ __forceinline__ void cp16(uint32_t dst_smem, const void* src) {
    asm volatile("cp.async.cg.shared.global [%0], [%1], 16;" :: "r"(dst_smem), "l"(src));
}
__device__ __forceinline__ void cp_commit() {
    asm volatile("cp.async.commit_group;");
}
__device__ __forceinline__ void cp_wait_all() {
    asm volatile("cp.async.wait_group 0;");
}

// named barriers (warp-granular groups; never use __syncthreads here)
__device__ __forceinline__ void bar_gemm() {       // warps 0-7 (256 threads)
    asm volatile("bar.sync 1, 256;" ::: "memory");
}
__device__ __forceinline__ void bar_csr() {        // warps 8-11 (128 threads)
    asm volatile("bar.sync 2, 128;" ::: "memory");
}

// ---------------------------------------------------------------------------
// Kernel 1 (merged): 256 blocks x 384 threads.
//   warps 0-7  : TF32 GEMM 128x64 tile (R12 body; cp.async double-buffered,
//                rna at fragment load, fused s epilogue) — bar.sync 1.
//   warps 8-11 : adjacency scan of 16 rows (MLP-8 float4, smem atomics)
//                — bar.sync 2. Runs CONCURRENTLY with the gemm warps, so
//                DRAM streaming overlaps tensor work inside every block.
// ---------------------------------------------------------------------------
#define GBM 128
#define GBN 64
#define GBK 32
#define GPAD 36
#define KITERS (INF_ / GBK)   // 8

__global__ __launch_bounds__(384, 2) void fused_gemm_csr(const float* __restrict__ x,
                                                         const float* __restrict__ W,
                                                         const float* __restrict__ a_src,
                                                         const float* __restrict__ a_dst,
                                                         const float* __restrict__ adj)
{
    __shared__ __align__(16) float As[2][GBM][GPAD];
    __shared__ __align__(16) float Bs[2][GBN][GPAD];
    __shared__ float sS[GBM], sD[GBM];
    __shared__ int cnt;

    const int bid = blockIdx.x;
    const int t   = threadIdx.x;

    // ================= CSR warps (threads 256..383) =================
    if (t >= 256) {
        const int ct = t - 256;              // 0..127
        const int n0 = bid * CSR_ROWS_PER_BLOCK;

        for (int r = 0; r < CSR_ROWS_PER_BLOCK; r++) {
            const int n = n0 + r;
            if (ct == 0) cnt = 0;
            bar_csr();

            const float4* row4 = reinterpret_cast<const float4*>(adj + (long long)n * N_);
            float4 v[8];
#pragma unroll
            for (int j = 0; j < 8; j++)
                v[j] = row4[ct + 128 * j];

#pragma unroll
            for (int j = 0; j < 8; j++) {
                const int base = (ct + 128 * j) * 4;
                if (v[j].x != 0.0f) { int p = atomicAdd(&cnt, 1); if (p < MAXD) g_nbrs[n * MAXD + p] = base + 0; }
                if (v[j].y != 0.0f) { int p = atomicAdd(&cnt, 1); if (p < MAXD) g_nbrs[n * MAXD + p] = base + 1; }
                if (v[j].z != 0.0f) { int p = atomicAdd(&cnt, 1); if (p < MAXD) g_nbrs[n * MAXD + p] = base + 2; }
                if (v[j].w != 0.0f) { int p = atomicAdd(&cnt, 1); if (p < MAXD) g_nbrs[n * MAXD + p] = base + 3; }
            }
            bar_csr();
            if (ct == 0) g_deg[n] = cnt < MAXD ? cnt : MAXD;
        }
        return;
    }

    // ================= GEMM warps (threads 0..255) =================
    const int head = bid & 3;
    const int bm   = (bid >> 2) * GBM;
    const int bo   = head * GBN;

    const int lane = t & 31;
    const int warp = t >> 5;
    const int wm   = warp >> 2;   // 0..1 -> 64-row slice
    const int wn   = warp & 3;    // 0..3 -> 16-col slice

    if (t < GBM) { sS[t] = 0.0f; sD[t] = 0.0f; }

    float acc[4][2][4];
#pragma unroll
    for (int mt = 0; mt < 4; mt++)
#pragma unroll
        for (int nt = 0; nt < 2; nt++)
#pragma unroll
            for (int i = 0; i < 4; i++) acc[mt][nt][i] = 0.0f;

    const int arow = t >> 3;          // 0..31
    const int acol = (t & 7) * 4;

    uint32_t asA[2][4], asB[2][2];
#pragma unroll
    for (int bufi = 0; bufi < 2; bufi++) {
#pragma unroll
        for (int j = 0; j < 4; j++)
            asA[bufi][j] = (uint32_t)__cvta_generic_to_shared(&As[bufi][arow + 32 * j][acol]);
#pragma unroll
        for (int j = 0; j < 2; j++)
            asB[bufi][j] = (uint32_t)__cvta_generic_to_shared(&Bs[bufi][arow + 32 * j][acol]);
    }

#pragma unroll
    for (int j = 0; j < 4; j++)
        cp16(asA[0][j], &x[(bm + arow + 32 * j) * INF_ + acol]);
#pragma unroll
    for (int j = 0; j < 2; j++)
        cp16(asB[0][j], &W[(bo + arow + 32 * j) * INF_ + acol]);
    cp_commit();

#pragma unroll
    for (int kt = 0; kt < KITERS; kt++) {
        const int cur = kt & 1;
        const int nxt = cur ^ 1;

        cp_wait_all();
        bar_gemm();

        if (kt + 1 < KITERS) {
            const int k0 = (kt + 1) * GBK;
#pragma unroll
            for (int j = 0; j < 4; j++)
                cp16(asA[nxt][j], &x[(bm + arow + 32 * j) * INF_ + k0 + acol]);
#pragma unroll
            for (int j = 0; j < 2; j++)
                cp16(asB[nxt][j], &W[(bo + arow + 32 * j) * INF_ + k0 + acol]);
            cp_commit();
        }

#pragma unroll
        for (int ks = 0; ks < 4; ks++) {
            const int kc = ks * 8 + (lane & 3);
            uint32_t Af[4][4];
#pragma unroll
            for (int mt = 0; mt < 4; mt++) {
                const int r0 = wm * 64 + mt * 16 + (lane >> 2);
                Af[mt][0] = tf32_rna(As[cur][r0][kc]);
                Af[mt][1] = tf32_rna(As[cur][r0 + 8][kc]);
                Af[mt][2] = tf32_rna(As[cur][r0][kc + 4]);
                Af[mt][3] = tf32_rna(As[cur][r0 + 8][kc + 4]);
            }
            uint32_t Bf[2][2];
#pragma unroll
            for (int nt = 0; nt < 2; nt++) {
                const int n0 = wn * 16 + nt * 8 + (lane >> 2);
                Bf[nt][0] = tf32_rna(Bs[cur][n0][kc]);
                Bf[nt][1] = tf32_rna(Bs[cur][n0][kc + 4]);
            }
#pragma unroll
            for (int mt = 0; mt < 4; mt++)
#pragma unroll
                for (int nt = 0; nt < 2; nt++)
                    mma_tf32(acc[mt][nt], Af[mt][0], Af[mt][1], Af[mt][2], Af[mt][3],
                             Bf[nt][0], Bf[nt][1]);
        }

        if (kt + 1 < KITERS) bar_gemm();   // nxt buffer staged; protect overwrite
    }

    // ---- epilogue A: fp16 h stores
#pragma unroll
    for (int mt = 0; mt < 4; mt++) {
#pragma unroll
        for (int nt = 0; nt < 2; nt++) {
            const int row = bm + wm * 64 + mt * 16 + (lane >> 2);
            const int col = bo + wn * 16 + nt * 8 + (lane & 3) * 2;
            float2 v0 = make_float2(acc[mt][nt][0], acc[mt][nt][1]);
            float2 v1 = make_float2(acc[mt][nt][2], acc[mt][nt][3]);
            *reinterpret_cast<__half2*>(&g_h16[row * HF_ + col]) = __float22half2_rn(v0);
            *reinterpret_cast<__half2*>(&g_h16[(row + 8) * HF_ + col]) = __float22half2_rn(v1);
        }
    }

    // ---- epilogue B: fused s_src/s_dst for this head
    float asv[2][2], adv[2][2];
#pragma unroll
    for (int nt = 0; nt < 2; nt++)
#pragma unroll
        for (int j = 0; j < 2; j++) {
            const int c = wn * 16 + nt * 8 + (lane & 3) * 2 + j;
            asv[nt][j] = a_src[head * F_ + c];
            adv[nt][j] = a_dst[head * F_ + c];
        }

    bar_gemm();
#pragma unroll
    for (int mt = 0; mt < 4; mt++) {
        float ps0 = 0.f, ps1 = 0.f, pd0 = 0.f, pd1 = 0.f;
#pragma unroll
        for (int nt = 0; nt < 2; nt++) {
            ps0 = fmaf(acc[mt][nt][0], asv[nt][0], ps0);
            ps0 = fmaf(acc[mt][nt][1], asv[nt][1], ps0);
            ps1 = fmaf(acc[mt][nt][2], asv[nt][0], ps1);
            ps1 = fmaf(acc[mt][nt][3], asv[nt][1], ps1);
            pd0 = fmaf(acc[mt][nt][0], adv[nt][0], pd0);
            pd0 = fmaf(acc[mt][nt][1], adv[nt][1], pd0);
            pd1 = fmaf(acc[mt][nt][2], adv[nt][0], pd1);
            pd1 = fmaf(acc[mt][nt][3], adv[nt][1], pd1);
        }
#pragma unroll
        for (int o = 1; o < 4; o <<= 1) {
            ps0 += __shfl_xor_sync(0xFFFFFFFFu, ps0, o);
            ps1 += __shfl_xor_sync(0xFFFFFFFFu, ps1, o);
            pd0 += __shfl_xor_sync(0xFFFFFFFFu, pd0, o);
            pd1 += __shfl_xor_sync(0xFFFFFFFFu, pd1, o);
        }
        if ((lane & 3) == 0) {
            const int r = wm * 64 + mt * 16 + (lane >> 2);
            atomicAdd(&sS[r], ps0);
            atomicAdd(&sS[r + 8], ps1);
            atomicAdd(&sD[r], pd0);
            atomicAdd(&sD[r + 8], pd1);
        }
    }
    bar_gemm();
    if (t < GBM) {
        g_ssrc[(bm + t) * H_ + head] = sS[t];
        g_sdst[(bm + t) * H_ + head] = sD[t];
    }
}

// ---------------------------------------------------------------------------
// packed-f32x2 accumulate (R16): 4 FFMA2 per gathered row, same numerics.
// ---------------------------------------------------------------------------
__device__ __forceinline__ void accum_row2(unsigned long long& a0, unsigned long long& a1,
                                           unsigned long long& a2, unsigned long long& a3,
                                           unsigned long long pd, const uint4& v)
{
    float2 f;
    unsigned long long g;
    f = __half22float2(*reinterpret_cast<const __half2*>(&v.x));
    asm("mov.b64 %0,{%1,%2};" : "=l"(g) : "f"(f.x), "f"(f.y));
    asm("fma.rn.f32x2 %0, %1, %2, %0;" : "+l"(a0) : "l"(g), "l"(pd));
    f = __half22float2(*reinterpret_cast<const __half2*>(&v.y));
    asm("mov.b64 %0,{%1,%2};" : "=l"(g) : "f"(f.x), "f"(f.y));
    asm("fma.rn.f32x2 %0, %1, %2, %0;" : "+l"(a1) : "l"(g), "l"(pd));
    f = __half22float2(*reinterpret_cast<const __half2*>(&v.z));
    asm("mov.b64 %0,{%1,%2};" : "=l"(g) : "f"(f.x), "f"(f.y));
    asm("fma.rn.f32x2 %0, %1, %2, %0;" : "+l"(a2) : "l"(g), "l"(pd));
    f = __half22float2(*reinterpret_cast<const __half2*>(&v.w));
    asm("mov.b64 %0,{%1,%2};" : "=l"(g) : "f"(f.x), "f"(f.y));
    asm("fma.rn.f32x2 %0, %1, %2, %0;" : "+l"(a3) : "l"(g), "l"(pd));
}

__device__ __forceinline__ unsigned long long dup_f32x2(float p) {
    unsigned long long d;
    asm("mov.b64 %0,{%1,%1};" : "=l"(d) : "f"(p));
    return d;
}

// ---------------------------------------------------------------------------
// Kernel 2 (attn, exact R16 form — 32.6us, ~94% of L2 roofline).
// ---------------------------------------------------------------------------
#define ATT_NPB 2

__global__ __launch_bounds__(128, 10) void attn_kernel(float* __restrict__ out)
{
    __shared__ __align__(16) int   nbS[ATT_NPB][MAXD_S];
    __shared__ __align__(16) float pS[4][H_ * PSTR];
    __shared__ int degS[ATT_NPB];

    const int t    = threadIdx.x;
    const int w    = t >> 5;
    const int lane = t & 31;
    const int b    = w & 1;
    const int nsub = w >> 1;
    const int n    = blockIdx.x * ATT_NPB + nsub;
    const int bn   = b * N_ + n;

    if (b == 0) {
        if (lane == 0) degS[nsub] = g_deg[n];
        const int dg = g_deg[n];
        for (int i = lane; i < dg && i < MAXD_S; i += 32)
            nbS[nsub][i] = g_nbrs[n * MAXD + i];
    }
    __syncthreads();

    const int deg  = degS[nsub];
    const int degc = deg < MAXD_S ? deg : MAXD_S;
    const int bN   = b * N_;

    const float4 c4 = *reinterpret_cast<const float4*>(&g_ssrc[bn * H_]);
    const float4* __restrict__ sd4 = reinterpret_cast<const float4*>(g_sdst);

    float4 sum4 = make_float4(0.f, 0.f, 0.f, 0.f);
    for (int i = lane; i < degc; i += 32) {
        const int m = nbS[nsub][i];
        float4 sdv = sd4[bN + m];
        float ex = c4.x + sdv.x, ey = c4.y + sdv.y, ez = c4.z + sdv.z, ew = c4.w + sdv.w;
        ex = fmaxf(ex, 0.2f * ex);
        ey = fmaxf(ey, 0.2f * ey);
        ez = fmaxf(ez, 0.2f * ez);
        ew = fmaxf(ew, 0.2f * ew);
        float px = __expf(ex), py = __expf(ey), pz = __expf(ez), pw = __expf(ew);
        pS[w][0 * PSTR + i] = px;
        pS[w][1 * PSTR + i] = py;
        pS[w][2 * PSTR + i] = pz;
        pS[w][3 * PSTR + i] = pw;
        sum4.x += px; sum4.y += py; sum4.z += pz; sum4.w += pw;
    }
    for (int i = degc + lane; i < deg; i += 32) {
        const int m = g_nbrs[n * MAXD + i];
        float4 sdv = sd4[bN + m];
        float ex = c4.x + sdv.x, ey = c4.y + sdv.y, ez = c4.z + sdv.z, ew = c4.w + sdv.w;
        ex = fmaxf(ex, 0.2f * ex);
        ey = fmaxf(ey, 0.2f * ey);
        ez = fmaxf(ez, 0.2f * ez);
        ew = fmaxf(ew, 0.2f * ew);
        sum4.x += __expf(ex); sum4.y += __expf(ey); sum4.z += __expf(ez); sum4.w += __expf(ew);
    }
#pragma unroll
    for (int o = 16; o > 0; o >>= 1) {
        sum4.x += __shfl_xor_sync(0xFFFFFFFFu, sum4.x, o);
        sum4.y += __shfl_xor_sync(0xFFFFFFFFu, sum4.y, o);
        sum4.z += __shfl_xor_sync(0xFFFFFFFFu, sum4.z, o);
        sum4.w += __shfl_xor_sync(0xFFFFFFFFu, sum4.w, o);
    }

    const int head = lane >> 3;
    float invh = (head & 2) ? ((head & 1) ? sum4.w : sum4.z)
                            : ((head & 1) ? sum4.y : sum4.x);
    invh = 1.0f / invh;

    __syncwarp();

    const uint4* __restrict__ hrow = reinterpret_cast<const uint4*>(g_h16) + (long long)bN * 32 + lane;
    const float* __restrict__ pw = &pS[w][head * PSTR];
    const int*   __restrict__ nbp = &nbS[nsub][0];

    unsigned long long a0 = 0ull, a1 = 0ull, a2 = 0ull, a3 = 0ull;

    int i = 0;
    for (; i + 4 <= degc; i += 4) {
        const int4   mm = *reinterpret_cast<const int4*>(&nbp[i]);
        const float4 pp = *reinterpret_cast<const float4*>(&pw[i]);
        const uint4 v0 = hrow[mm.x * 32];
        const uint4 v1 = hrow[mm.y * 32];
        const uint4 v2 = hrow[mm.z * 32];
        const uint4 v3 = hrow[mm.w * 32];
        accum_row2(a0, a1, a2, a3, dup_f32x2(pp.x), v0);
        accum_row2(a0, a1, a2, a3, dup_f32x2(pp.y), v1);
        accum_row2(a0, a1, a2, a3, dup_f32x2(pp.z), v2);
        accum_row2(a0, a1, a2, a3, dup_f32x2(pp.w), v3);
    }
    for (; i < degc; i++) {
        const uint4 v0 = hrow[nbp[i] * 32];
        accum_row2(a0, a1, a2, a3, dup_f32x2(pw[i]), v0);
    }
    for (i = degc; i < deg; i++) {
        const int m0 = g_nbrs[n * MAXD + i];
        float4 sdv = sd4[bN + m0];
        float e = ((head & 2) ? ((head & 1) ? c4.w + sdv.w : c4.z + sdv.z)
                              : ((head & 1) ? c4.y + sdv.y : c4.x + sdv.x));
        e = fmaxf(e, 0.2f * e);
        const uint4 v0 = hrow[m0 * 32];
        accum_row2(a0, a1, a2, a3, dup_f32x2(__expf(e)), v0);
    }

    float2 f0, f1, f2, f3;
    asm("mov.b64 {%0,%1}, %2;" : "=f"(f0.x), "=f"(f0.y) : "l"(a0));
    asm("mov.b64 {%0,%1}, %2;" : "=f"(f1.x), "=f"(f1.y) : "l"(a1));
    asm("mov.b64 {%0,%1}, %2;" : "=f"(f2.x), "=f"(f2.y) : "l"(a2));
    asm("mov.b64 {%0,%1}, %2;" : "=f"(f3.x), "=f"(f3.y) : "l"(a3));

    float4 o0 = make_float4(f0.x * invh, f0.y * invh, f1.x * invh, f1.y * invh);
    float4 o1 = make_float4(f2.x * invh, f2.y * invh, f3.x * invh, f3.y * invh);
    float4* outp = reinterpret_cast<float4*>(out);
    outp[bn * 64 + lane * 2 + 0] = o0;
    outp[bn * 64 + lane * 2 + 1] = o1;
}

// ---------------------------------------------------------------------------
extern "C" void kernel_launch(void* const* d_in, const int* in_sizes, int n_in,
                              void* d_out, int out_size)
{
    const float* x     = (const float*)d_in[0];
    const float* adj   = (const float*)d_in[1];
    const float* W     = (const float*)d_in[2];
    const float* a_src = (const float*)d_in[3];
    const float* a_dst = (const float*)d_in[4];
    float* out = (float*)d_out;

    fused_gemm_csr<<<FUSED_BLOCKS, 384>>>(x, W, a_src, a_dst, adj);
    attn_kernel<<<N_ / ATT_NPB, 128>>>(out);
}